// round 9
// baseline (speedup 1.0000x reference)
#include <cuda_runtime.h>
#include <cuda_bf16.h>
#include <math.h>
#include <stdint.h>

#define BATCH 16
#define CCH   256
#define NSP   4096   // 64*64
#define CSP   32     // C/8
#define NPOOL 1024   // 32*32

// ---------------- scratch ----------------
__device__ float g_kT[BATCH * NSP * CSP];                    //  8 MB tf32 (B, n, 32)
__device__ float g_qT[BATCH * NPOOL * CSP];                  //  2 MB tf32 (B, np, 32)
__device__ float g_xr[(size_t)BATCH * CCH * NSP];            // 64 MB tf32-RN copy of x
__device__ float g_wvr[CCH * CCH];                           // 256 KB tf32-RN wv
__device__ float g_wor[CCH * CCH];                           // 256 KB tf32-RN wo
__device__ float g_vpool[BATCH * CCH * NPOOL];               // 16 MB (tf32-RN values)
__device__ float g_vprime[BATCH * CCH * NPOOL];              // 16 MB
__device__ float g_part[BATCH * 32 * NPOOL];                 //  2 MB
__device__ float g_invden[BATCH * NPOOL];                    // 64 KB
__device__ __nv_bfloat16 g_attnh[(size_t)BATCH * NSP * NPOOL]; // 128 MB
__device__ __nv_bfloat16 g_vppb[BATCH * CCH * NPOOL];        //  8 MB

// ---------------- helpers ----------------
__device__ __forceinline__ float tf32_rn(float v) {
    uint32_t u;
    asm("cvt.rna.tf32.f32 %0, %1;" : "=r"(u) : "f"(v));
    return __uint_as_float(u);
}
__device__ __forceinline__ void mma_tf32(float* c, const uint32_t* a, const uint32_t* b) {
    asm volatile(
        "mma.sync.aligned.m16n8k8.row.col.f32.tf32.tf32.f32 "
        "{%0,%1,%2,%3}, {%4,%5,%6,%7}, {%8,%9}, {%0,%1,%2,%3};"
        : "+f"(c[0]), "+f"(c[1]), "+f"(c[2]), "+f"(c[3])
        : "r"(a[0]), "r"(a[1]), "r"(a[2]), "r"(a[3]), "r"(b[0]), "r"(b[1]));
}
__device__ __forceinline__ void mma_bf16(float* c, const uint32_t* a, const uint32_t* b) {
    asm volatile(
        "mma.sync.aligned.m16n8k16.row.col.f32.bf16.bf16.f32 "
        "{%0,%1,%2,%3}, {%4,%5,%6,%7}, {%8,%9}, {%0,%1,%2,%3};"
        : "+f"(c[0]), "+f"(c[1]), "+f"(c[2]), "+f"(c[3])
        : "r"(a[0]), "r"(a[1]), "r"(a[2]), "r"(a[3]), "r"(b[0]), "r"(b[1]));
}
__device__ __forceinline__ void cpa16(uint32_t dst, const void* src) {
    asm volatile("cp.async.cg.shared.global [%0], [%1], 16;" :: "r"(dst), "l"(src));
}

// ---------------- pre-round producers to tf32-RN ----------------
__global__ void round4_k(const float* __restrict__ in, float* __restrict__ outp)
{
    size_t i = ((size_t)blockIdx.x * 256 + threadIdx.x) * 4;
    float4 v = *(const float4*)&in[i];
    v.x = tf32_rn(v.x); v.y = tf32_rn(v.y);
    v.z = tf32_rn(v.z); v.w = tf32_rn(v.w);
    *(float4*)&outp[i] = v;
}
__global__ void round_w_k(const float* __restrict__ wv, const float* __restrict__ wo,
                          float* __restrict__ wvr, float* __restrict__ wor)
{
    int i = (blockIdx.x * 256 + threadIdx.x) * 4;
    float4 a = *(const float4*)&wv[i];
    a.x = tf32_rn(a.x); a.y = tf32_rn(a.y); a.z = tf32_rn(a.z); a.w = tf32_rn(a.w);
    *(float4*)&wvr[i] = a;
    float4 b = *(const float4*)&wo[i];
    b.x = tf32_rn(b.x); b.y = tf32_rn(b.y); b.z = tf32_rn(b.z); b.w = tf32_rn(b.w);
    *(float4*)&wor[i] = b;
}

// ============ conv_qk via tf32 mma: kT (B,n,32) + pooled qT (B,np,32) ============
__global__ __launch_bounds__(256)
void conv_qk_mma(const float* __restrict__ wk, const float* __restrict__ bk,
                 const float* __restrict__ wq, const float* __restrict__ bq,
                 const float* __restrict__ x,
                 float* __restrict__ kT, float* __restrict__ qT)
{
    __shared__ union {
        struct { float sA[64 * 20]; float sB[128 * 20]; } ld;
        float sOut[64 * 132];
    } sh;

    const int b    = blockIdx.z;
    const int col0 = blockIdx.x * 128;
    const float* xb = x + (size_t)b * CCH * NSP;
    const int tid = threadIdx.x, lane = tid & 31, wid = tid >> 5;
    const int wr = wid >> 2, wc = wid & 3;
    const int g = lane >> 2, tk = lane & 3;

    float cf[2][4][4] = {};

    for (int k0 = 0; k0 < CCH; k0 += 16) {
        {
            int r = tid >> 2, kq = (tid & 3) * 4;
            const float* wrow = (r < 32) ? (wk + r * CCH) : (wq + (r - 32) * CCH);
            float4 v = *(const float4*)&wrow[k0 + kq];
            v.x = tf32_rn(v.x); v.y = tf32_rn(v.y);
            v.z = tf32_rn(v.z); v.w = tf32_rn(v.w);
            *(float4*)&sh.ld.sA[r * 20 + kq] = v;
        }
#pragma unroll
        for (int u = 0; u < 2; u++) {
            int idx = tid + u * 256;
            int kr = idx >> 5, nc = (idx & 31) * 4;
            float4 v = *(const float4*)&xb[(size_t)(k0 + kr) * NSP + col0 + nc];
            sh.ld.sB[(nc + 0) * 20 + kr] = tf32_rn(v.x);
            sh.ld.sB[(nc + 1) * 20 + kr] = tf32_rn(v.y);
            sh.ld.sB[(nc + 2) * 20 + kr] = tf32_rn(v.z);
            sh.ld.sB[(nc + 3) * 20 + kr] = tf32_rn(v.w);
        }
        __syncthreads();
#pragma unroll
        for (int ks = 0; ks < 2; ks++) {
            const int ko = ks * 8;
            uint32_t a[2][4], bf[4][2];
#pragma unroll
            for (int i = 0; i < 2; i++) {
                const int ra = (wr * 32 + i * 16 + g) * 20 + ko + tk;
                a[i][0] = __float_as_uint(sh.ld.sA[ra]);
                a[i][1] = __float_as_uint(sh.ld.sA[ra + 8 * 20]);
                a[i][2] = __float_as_uint(sh.ld.sA[ra + 4]);
                a[i][3] = __float_as_uint(sh.ld.sA[ra + 8 * 20 + 4]);
            }
#pragma unroll
            for (int j = 0; j < 4; j++) {
                const int rb = (wc * 32 + j * 8 + g) * 20 + ko + tk;
                bf[j][0] = __float_as_uint(sh.ld.sB[rb]);
                bf[j][1] = __float_as_uint(sh.ld.sB[rb + 4]);
            }
#pragma unroll
            for (int i = 0; i < 2; i++)
#pragma unroll
                for (int j = 0; j < 4; j++) mma_tf32(cf[i][j], a[i], bf[j]);
        }
        __syncthreads();
    }

#pragma unroll
    for (int i = 0; i < 2; i++)
#pragma unroll
        for (int half = 0; half < 2; half++) {
            const int r = wr * 32 + i * 16 + half * 8 + g;
#pragma unroll
            for (int j = 0; j < 4; j++) {
                const int c = wc * 32 + j * 8 + 2 * tk;
                sh.sOut[r * 132 + c]     = cf[i][j][half * 2 + 0];
                sh.sOut[r * 132 + c + 1] = cf[i][j][half * 2 + 1];
            }
        }
    __syncthreads();

    float* kTb = kT + (size_t)b * NSP * CSP;
#pragma unroll
    for (int u = 0; u < 4; u++) {
        int idx = tid + u * 256;
        int nn = idx >> 3, csq = (idx & 7) * 4;
        float4 o;
        o.x = tf32_rn(sh.sOut[(csq + 0) * 132 + nn] + bk[csq + 0]);
        o.y = tf32_rn(sh.sOut[(csq + 1) * 132 + nn] + bk[csq + 1]);
        o.z = tf32_rn(sh.sOut[(csq + 2) * 132 + nn] + bk[csq + 2]);
        o.w = tf32_rn(sh.sOut[(csq + 3) * 132 + nn] + bk[csq + 3]);
        *(float4*)&kTb[(size_t)(col0 + nn) * CSP + csq] = o;
    }

    float* qTb = qT + (size_t)b * NPOOL * CSP;
    const int hp = col0 >> 7;
    {
        int wp = tid >> 3, csq = (tid & 7) * 4;
        float4 o;
        float* oc = &o.x;
#pragma unroll
        for (int t = 0; t < 4; t++) {
            const int cs = csq + t;
            const float* r = &sh.sOut[(32 + cs) * 132];
            float v = fmaxf(fmaxf(r[2 * wp], r[2 * wp + 1]),
                            fmaxf(r[64 + 2 * wp], r[64 + 2 * wp + 1]));
            oc[t] = tf32_rn(v + bq[cs]);
        }
        *(float4*)&qTb[(size_t)(hp * 32 + wp) * CSP + csq] = o;
    }
}

// ============ energy via tf32 mma + exp -> bf16 + partials ====
__global__ __launch_bounds__(256)
void energy_mma(const float* __restrict__ kTg, const float* __restrict__ qTg,
                __nv_bfloat16* __restrict__ attnh, float* __restrict__ part)
{
    __shared__ float sA[128 * 36];
    __shared__ float sB[128 * 36];
    __shared__ float sX[16 * 132];

    const int b  = blockIdx.z;
    const int m0 = blockIdx.y * 128;
    const int n0 = blockIdx.x * 128;
    const float* Ab = kTg + ((size_t)b * NSP + m0) * CSP;
    const float* Bb = qTg + ((size_t)b * NPOOL + n0) * CSP;

    const int tid = threadIdx.x, lane = tid & 31, wid = tid >> 5;
    const int wr = wid >> 2, wc = wid & 3;
    const int g = lane >> 2, tk = lane & 3;

#pragma unroll
    for (int u = 0; u < 4; u++) {
        int idx = tid + u * 256;
        int r = idx >> 3, kq = (idx & 7) * 4;
        *(float4*)&sA[r * 36 + kq] = *(const float4*)&Ab[(size_t)r * CSP + kq];
        *(float4*)&sB[r * 36 + kq] = *(const float4*)&Bb[(size_t)r * CSP + kq];
    }
    __syncthreads();

    float cf[4][4][4] = {};
#pragma unroll
    for (int ks = 0; ks < 4; ks++) {
        const int ko = ks * 8;
        uint32_t a[4][4], bf[4][2];
#pragma unroll
        for (int i = 0; i < 4; i++) {
            const int ra = (wr * 64 + i * 16 + g) * 36 + ko + tk;
            a[i][0] = __float_as_uint(sA[ra]);
            a[i][1] = __float_as_uint(sA[ra + 8 * 36]);
            a[i][2] = __float_as_uint(sA[ra + 4]);
            a[i][3] = __float_as_uint(sA[ra + 8 * 36 + 4]);
        }
#pragma unroll
        for (int j = 0; j < 4; j++) {
            const int rb = (wc * 32 + j * 8 + g) * 36 + ko + tk;
            bf[j][0] = __float_as_uint(sB[rb]);
            bf[j][1] = __float_as_uint(sB[rb + 4]);
        }
#pragma unroll
        for (int i = 0; i < 4; i++)
#pragma unroll
            for (int j = 0; j < 4; j++) mma_tf32(cf[i][j], a[i], bf[j]);
    }

    __nv_bfloat16* Cb = attnh + (size_t)b * NSP * NPOOL;
    float colsum[4][2] = {};
#pragma unroll
    for (int i = 0; i < 4; i++) {
#pragma unroll
        for (int half = 0; half < 2; half++) {
            const int r = m0 + wr * 64 + i * 16 + g + half * 8;
            const size_t ro = (size_t)r * NPOOL;
#pragma unroll
            for (int j = 0; j < 4; j++) {
                const int c = n0 + wc * 32 + j * 8 + 2 * tk;
                float e0 = __expf(cf[i][j][half * 2 + 0]);
                float e1 = __expf(cf[i][j][half * 2 + 1]);
                colsum[j][0] += e0;
                colsum[j][1] += e1;
                *(__nv_bfloat162*)&Cb[ro + c] = __floats2bfloat162_rn(e0, e1);
            }
        }
    }
#pragma unroll
    for (int j = 0; j < 4; j++) {
        const int col = wc * 32 + j * 8 + 2 * tk;
        sX[(wr * 8 + g) * 132 + col]     = colsum[j][0];
        sX[(wr * 8 + g) * 132 + col + 1] = colsum[j][1];
    }
    __syncthreads();
    if (tid < 128) {
        float t = 0.f;
#pragma unroll
        for (int k = 0; k < 16; k++) t += sX[k * 132 + tid];
        part[((size_t)b * 32 + blockIdx.y) * NPOOL + n0 + tid] = t;
    }
}

// ================= V-branch GEMM v2 (inputs pre-rounded tf32-RN) ============
// C = A(MxK, K-contig, unbatched) @ B(KxN, N-contig, batched) [+bias]
// EPI 0: fp32 (+bias) -> C (B,M,N)
// EPI 1: 2x2 maxpool + bias, tf32-RN rounded -> C (B,M,N/4)
#define GV_SA 2560          // 128*20 floats per buffer
#define GV_SB 2176          // 16*136 floats per buffer
template<int EPI>
__global__ __launch_bounds__(256)
void gemm_v2(const float* __restrict__ A,
             const float* __restrict__ B,
             const float* __restrict__ bias,
             float* __restrict__ C,
             int M, int N, int K)
{
    __shared__ float sm[2 * GV_SA + 2 * GV_SB];
    float* sX = sm;

    const int b  = blockIdx.z;
    const int r0 = blockIdx.y * 128;
    const int n0 = blockIdx.x * 128;
    const float* Ab = A;
    const float* Bb = B + (size_t)b * K * N;

    const int tid = threadIdx.x, lane = tid & 31, wid = tid >> 5;
    const int wr = wid >> 2, wc = wid & 3;
    const int g = lane >> 2, tk = lane & 3;

    const int a_r = tid >> 1, a_q = (tid & 1) * 2;
    const uint32_t smBase = (uint32_t)__cvta_generic_to_shared(sm);

    auto issue = [&](int k0, int s) {
#pragma unroll
        for (int u = 0; u < 2; u++) {
            int q = a_q + u;
            cpa16(smBase + (s * GV_SA + a_r * 20 + q * 4) * 4,
                  &Ab[(size_t)(r0 + a_r) * K + k0 + q * 4]);
        }
#pragma unroll
        for (int u = 0; u < 2; u++) {
            int idx = tid + u * 256;
            int kr = idx >> 5, nc = (idx & 31) * 4;
            cpa16(smBase + (2 * GV_SA + s * GV_SB + kr * 136 + nc) * 4,
                  &Bb[(size_t)(k0 + kr) * N + n0 + nc]);
        }
        asm volatile("cp.async.commit_group;");
    };

    float cf[4][4][4] = {};
    const int NIT = K / 16;

    issue(0, 0);
    for (int kt = 0; kt < NIT; kt++) {
        const int cur = kt & 1;
        if (kt < NIT - 1) {
            issue((kt + 1) * 16, cur ^ 1);
            asm volatile("cp.async.wait_group 1;");
        } else {
            asm volatile("cp.async.wait_group 0;");
        }
        __syncthreads();

        const float* cA = sm + cur * GV_SA;
        const float* cB = sm + 2 * GV_SA + cur * GV_SB;
#pragma unroll
        for (int ks = 0; ks < 2; ks++) {
            const int ko = ks * 8;
            uint32_t a[4][4], bf[4][2];
#pragma unroll
            for (int i = 0; i < 4; i++) {
                const int ra = (wr * 64 + i * 16 + g) * 20 + ko + tk;
                a[i][0] = __float_as_uint(cA[ra]);
                a[i][1] = __float_as_uint(cA[ra + 8 * 20]);
                a[i][2] = __float_as_uint(cA[ra + 4]);
                a[i][3] = __float_as_uint(cA[ra + 8 * 20 + 4]);
            }
#pragma unroll
            for (int j = 0; j < 4; j++) {
                const int nn = wc * 32 + j * 8 + g;
                bf[j][0] = __float_as_uint(cB[(ko + tk) * 136 + nn]);
                bf[j][1] = __float_as_uint(cB[(ko + tk + 4) * 136 + nn]);
            }
#pragma unroll
            for (int i = 0; i < 4; i++)
#pragma unroll
                for (int j = 0; j < 4; j++) mma_tf32(cf[i][j], a[i], bf[j]);
        }
        __syncthreads();
    }

    if (EPI == 0) {
        float* Cb = C + (size_t)b * M * N;
#pragma unroll
        for (int i = 0; i < 4; i++)
#pragma unroll
            for (int half = 0; half < 2; half++) {
                const int r = r0 + wr * 64 + i * 16 + g + half * 8;
                const float bv = (bias != nullptr) ? bias[r] : 0.f;
                const size_t ro = (size_t)r * N;
#pragma unroll
                for (int j = 0; j < 4; j++) {
                    const int c = n0 + wc * 32 + j * 8 + 2 * tk;
                    float2 o;
                    o.x = cf[i][j][half * 2 + 0] + bv;
                    o.y = cf[i][j][half * 2 + 1] + bv;
                    *(float2*)&Cb[ro + c] = o;
                }
            }
    }

    if (EPI == 1) {
        float* Cp = C + (size_t)b * M * (N / 4);
        const int pcb = n0 >> 2;
#pragma unroll 1
        for (int s = 0; s < 4; s++) {
            if (wr == (s >> 1)) {
#pragma unroll
                for (int ii = 0; ii < 2; ii++) {
                    const int i = (s & 1) * 2 + ii;
#pragma unroll
                    for (int half = 0; half < 2; half++) {
                        const int lr = ii * 16 + half * 8 + g;
#pragma unroll
                        for (int j = 0; j < 4; j++) {
                            const int col = wc * 32 + j * 8 + 2 * tk;
                            sX[lr * 132 + col]     = cf[i][j][half * 2 + 0];
                            sX[lr * 132 + col + 1] = cf[i][j][half * 2 + 1];
                        }
                    }
                }
            }
            __syncthreads();
#pragma unroll
            for (int u = 0; u < 4; u++) {
                int po = tid + u * 256;
                int rr = po >> 5, pc = po & 31;
                float v = fmaxf(fmaxf(sX[rr * 132 + 2 * pc], sX[rr * 132 + 2 * pc + 1]),
                                fmaxf(sX[rr * 132 + 64 + 2 * pc], sX[rr * 132 + 64 + 2 * pc + 1]));
                const int r = r0 + s * 32 + rr;
                // round result (+bias) to tf32-RN: it feeds the next tf32 GEMM
                Cp[(size_t)r * (N / 4) + pcb + pc] = tf32_rn(v + bias[r]);
            }
            __syncthreads();
        }
    }
}

// ---------------- denominator + v'' ----------------
__global__ void invden_k(const float* __restrict__ part, float* __restrict__ invden)
{
    int idx = blockIdx.x * 256 + threadIdx.x;
    int b  = idx >> 10;
    int np = idx & 1023;
    const float* p = part + (size_t)b * 32 * NPOOL + np;
    float s = 0.f;
#pragma unroll
    for (int i = 0; i < 32; i++) s += p[(size_t)i * NPOOL];
    invden[idx] = 1.f / s;
}

__global__ void scale_v_k(const float* __restrict__ vpr,
                          const float* __restrict__ invden,
                          __nv_bfloat16* __restrict__ vppb)
{
    int idx = blockIdx.x * 256 + threadIdx.x;
    int np = idx & 1023;
    int b  = idx >> 18;
    vppb[idx] = __float2bfloat16_rn(vpr[idx] * invden[b * NPOOL + np]);
}

// ============ final bf16 mma: 128x128 tiles (c split), cp.async ===========
#define FSTRIDE 12
__global__ __launch_bounds__(256)
void final3_k(const __nv_bfloat16* __restrict__ vpp,
              const __nv_bfloat16* __restrict__ pm,
              const float* __restrict__ bo,
              const float* __restrict__ gamma,
              const float* __restrict__ xres,
              float* __restrict__ out)
{
    __shared__ uint32_t uA[2][128 * FSTRIDE];
    __shared__ uint32_t uB[2][128 * FSTRIDE];

    const int tid = threadIdx.x, lane = tid & 31, wid = tid >> 5;
    const int b   = blockIdx.z;
    const int m0  = blockIdx.x * 128;
    const int c00 = blockIdx.y * 128;
    const int wr = wid >> 1;
    const int wc = wid & 1;
    const int g = lane >> 2, tk = lane & 3;

    const __nv_bfloat16* Ab = vpp + ((size_t)b * CCH + c00) * NPOOL;
    const __nv_bfloat16* Bb = pm + ((size_t)b * NSP + m0) * NPOOL;

    const int lr = tid >> 1, lq = tid & 1;
    uint32_t aDst = (uint32_t)__cvta_generic_to_shared(&uA[0][lr * FSTRIDE + lq * 4]);
    uint32_t bDst = (uint32_t)__cvta_generic_to_shared(&uB[0][lr * FSTRIDE + lq * 4]);
    const uint32_t stepA = 128 * FSTRIDE * 4;

    float cf[2][8][4] = {};

    auto issue = [&](int kt, int s) {
        const int kb = kt * 16;
        cpa16(aDst + s * stepA, &Ab[(size_t)lr * NPOOL + kb + lq * 8]);
        cpa16(bDst + s * stepA, &Bb[(size_t)lr * NPOOL + kb + lq * 8]);
        asm volatile("cp.async.commit_group;");
    };

    issue(0, 0);
    for (int kt = 0; kt < NPOOL / 16; kt++) {
        const int cur = kt & 1;
        if (kt < NPOOL / 16 - 1) {
            issue(kt + 1, cur ^ 1);
            asm volatile("cp.async.wait_group 1;");
        } else {
            asm volatile("cp.async.wait_group 0;");
        }
        __syncthreads();

        uint32_t a[2][4], bf[8][2];
#pragma unroll
        for (int i = 0; i < 2; i++) {
            const int ra = (wr * 32 + i * 16 + g) * FSTRIDE + tk;
            a[i][0] = uA[cur][ra];
            a[i][1] = uA[cur][ra + 8 * FSTRIDE];
            a[i][2] = uA[cur][ra + 4];
            a[i][3] = uA[cur][ra + 8 * FSTRIDE + 4];
        }
#pragma unroll
        for (int j = 0; j < 8; j++) {
            const int rb = (wc * 64 + j * 8 + g) * FSTRIDE + tk;
            bf[j][0] = uB[cur][rb];
            bf[j][1] = uB[cur][rb + 4];
        }
#pragma unroll
        for (int i = 0; i < 2; i++)
#pragma unroll
            for (int j = 0; j < 8; j++) mma_bf16(cf[i][j], a[i], bf[j]);
        __syncthreads();
    }

    const float gm = gamma[0];
#pragma unroll
    for (int i = 0; i < 2; i++) {
#pragma unroll
        for (int half = 0; half < 2; half++) {
            const int c = c00 + wr * 32 + i * 16 + g + half * 8;
            const float bc = bo[c];
            const size_t ro = ((size_t)b * CCH + c) * NSP;
#pragma unroll
            for (int j = 0; j < 8; j++) {
                const int m = m0 + wc * 64 + j * 8 + 2 * tk;
                float2 xr = *(const float2*)&xres[ro + m];
                float2 o;
                o.x = gm * (cf[i][j][half * 2 + 0] + bc) + xr.x;
                o.y = gm * (cf[i][j][half * 2 + 1] + bc) + xr.y;
                *(float2*)&out[ro + m] = o;
            }
        }
    }
}

// ---------------- launch ----------------
extern "C" void kernel_launch(void* const* d_in, const int* in_sizes, int n_in,
                              void* d_out, int out_size)
{
    const float* x     = (const float*)d_in[0];
    const float* wq    = (const float*)d_in[1];
    const float* bq    = (const float*)d_in[2];
    const float* wk    = (const float*)d_in[3];
    const float* bk    = (const float*)d_in[4];
    const float* wv    = (const float*)d_in[5];
    const float* bv    = (const float*)d_in[6];
    const float* wo    = (const float*)d_in[7];
    const float* bo    = (const float*)d_in[8];
    const float* gamma = (const float*)d_in[9];
    float* out = (float*)d_out;

    float *pkT, *pqT, *pxr, *pwvr, *pwor, *pvp, *pvpr, *ppart, *pinv;
    __nv_bfloat16 *pattnh, *pvppb;
    cudaGetSymbolAddress((void**)&pkT,    g_kT);
    cudaGetSymbolAddress((void**)&pqT,    g_qT);
    cudaGetSymbolAddress((void**)&pxr,    g_xr);
    cudaGetSymbolAddress((void**)&pwvr,   g_wvr);
    cudaGetSymbolAddress((void**)&pwor,   g_wor);
    cudaGetSymbolAddress((void**)&pvp,    g_vpool);
    cudaGetSymbolAddress((void**)&pvpr,   g_vprime);
    cudaGetSymbolAddress((void**)&ppart,  g_part);
    cudaGetSymbolAddress((void**)&pinv,   g_invden);
    cudaGetSymbolAddress((void**)&pattnh, g_attnh);
    cudaGetSymbolAddress((void**)&pvppb,  g_vppb);

    static cudaStream_t s1 = nullptr;
    static cudaEvent_t evFork = nullptr, evJoin = nullptr;
    if (s1 == nullptr) {
        cudaStreamCreateWithFlags(&s1, cudaStreamNonBlocking);
        cudaEventCreateWithFlags(&evFork, cudaEventDisableTiming);
        cudaEventCreateWithFlags(&evJoin, cudaEventDisableTiming);
    }

    cudaEventRecord(evFork, 0);
    cudaStreamWaitEvent(s1, evFork, 0);

    // --- s1: V branch (pre-round producers, then tf32 mma GEMMs) ---
    round4_k<<<(BATCH * CCH * NSP) / 1024, 256, 0, s1>>>(x, pxr);
    round_w_k<<<(CCH * CCH) / 1024, 256, 0, s1>>>(wv, wo, pwvr, pwor);
    {   // vpool = tf32_rn(maxpool(wvr @ xr) + bv)
        dim3 g(NSP / 128, CCH / 128, BATCH);
        gemm_v2<1><<<g, 256, 0, s1>>>(pwvr, pxr, bv, pvp, CCH, NSP, CCH);
    }
    {   // v' = wor @ vpool (fp32 out)
        dim3 g(NPOOL / 128, CCH / 128, BATCH);
        gemm_v2<0><<<g, 256, 0, s1>>>(pwor, pvp, nullptr, pvpr, CCH, NPOOL, CCH);
    }
    cudaEventRecord(evJoin, s1);

    // --- main: conv_qk (mma) -> energy (mma, exp->bf16) -> invden ---
    {
        dim3 g(NSP / 128, 1, BATCH);
        conv_qk_mma<<<g, 256>>>(wk, bk, wq, bq, x, pkT, pqT);
    }
    {
        dim3 g(NPOOL / 128, NSP / 128, BATCH);
        energy_mma<<<g, 256>>>(pkT, pqT, pattnh, ppart);
    }
    invden_k<<<BATCH * NPOOL / 256, 256>>>(ppart, pinv);

    cudaStreamWaitEvent(0, evJoin, 0);
    scale_v_k<<<BATCH * CCH * NPOOL / 256, 256>>>(pvpr, pinv, pvppb);
    {
        dim3 g(NSP / 128, CCH / 128, BATCH);
        final3_k<<<g, 256>>>(pvppb, pattnh, bo, gamma, x, out);
    }
}

// round 10
// speedup vs baseline: 1.3857x; 1.3857x over previous
#include <cuda_runtime.h>
#include <cuda_bf16.h>
#include <math.h>
#include <stdint.h>

#define BATCH 16
#define CCH   256
#define NSP   4096   // 64*64
#define CSP   32     // C/8
#define NPOOL 1024   // 32*32

// ---------------- scratch ----------------
__device__ float g_kT[BATCH * NSP * CSP];                    //  8 MB tf32 (B, n, 32)
__device__ float g_qT[BATCH * NPOOL * CSP];                  //  2 MB tf32 (B, np, 32)
__device__ float g_xr[(size_t)BATCH * CCH * NSP];            // 64 MB tf32-RN copy of x
__device__ float g_wvr[CCH * CCH];                           // 256 KB tf32-RN wv
__device__ float g_wor[CCH * CCH];                           // 256 KB tf32-RN wo
__device__ float g_vpool[BATCH * CCH * NPOOL];               // 16 MB (tf32-RN values)
__device__ float g_vprime[BATCH * CCH * NPOOL];              // 16 MB
__device__ float g_part[BATCH * 32 * NPOOL];                 //  2 MB
__device__ float g_invden[BATCH * NPOOL];                    // 64 KB
__device__ __nv_bfloat16 g_attnh[(size_t)BATCH * NSP * NPOOL]; // 128 MB
__device__ __nv_bfloat16 g_vppb[BATCH * CCH * NPOOL];        //  8 MB

// ---------------- helpers ----------------
__device__ __forceinline__ float tf32_rn(float v) {
    uint32_t u;
    asm("cvt.rna.tf32.f32 %0, %1;" : "=r"(u) : "f"(v));
    return __uint_as_float(u);
}
__device__ __forceinline__ void mma_tf32(float* c, const uint32_t* a, const uint32_t* b) {
    asm volatile(
        "mma.sync.aligned.m16n8k8.row.col.f32.tf32.tf32.f32 "
        "{%0,%1,%2,%3}, {%4,%5,%6,%7}, {%8,%9}, {%0,%1,%2,%3};"
        : "+f"(c[0]), "+f"(c[1]), "+f"(c[2]), "+f"(c[3])
        : "r"(a[0]), "r"(a[1]), "r"(a[2]), "r"(a[3]), "r"(b[0]), "r"(b[1]));
}
__device__ __forceinline__ void mma_bf16(float* c, const uint32_t* a, const uint32_t* b) {
    asm volatile(
        "mma.sync.aligned.m16n8k16.row.col.f32.bf16.bf16.f32 "
        "{%0,%1,%2,%3}, {%4,%5,%6,%7}, {%8,%9}, {%0,%1,%2,%3};"
        : "+f"(c[0]), "+f"(c[1]), "+f"(c[2]), "+f"(c[3])
        : "r"(a[0]), "r"(a[1]), "r"(a[2]), "r"(a[3]), "r"(b[0]), "r"(b[1]));
}
__device__ __forceinline__ void cpa16(uint32_t dst, const void* src) {
    asm volatile("cp.async.cg.shared.global [%0], [%1], 16;" :: "r"(dst), "l"(src));
}

// ---------------- pre-round weights to tf32-RN (tiny) ----------------
__global__ void round_w_k(const float* __restrict__ wv, const float* __restrict__ wo,
                          float* __restrict__ wvr, float* __restrict__ wor)
{
    int i = (blockIdx.x * 256 + threadIdx.x) * 4;
    float4 a = *(const float4*)&wv[i];
    a.x = tf32_rn(a.x); a.y = tf32_rn(a.y); a.z = tf32_rn(a.z); a.w = tf32_rn(a.w);
    *(float4*)&wvr[i] = a;
    float4 b = *(const float4*)&wo[i];
    b.x = tf32_rn(b.x); b.y = tf32_rn(b.y); b.z = tf32_rn(b.z); b.w = tf32_rn(b.w);
    *(float4*)&wor[i] = b;
}

// ============ conv_qk via tf32 mma: kT + pooled qT + rounded-x side stream ====
__global__ __launch_bounds__(256)
void conv_qk_mma(const float* __restrict__ wk, const float* __restrict__ bk,
                 const float* __restrict__ wq, const float* __restrict__ bq,
                 const float* __restrict__ x,
                 float* __restrict__ kT, float* __restrict__ qT,
                 float* __restrict__ xr)
{
    __shared__ union {
        struct { float sA[64 * 20]; float sB[128 * 20]; } ld;
        float sOut[64 * 132];
    } sh;

    const int b    = blockIdx.z;
    const int col0 = blockIdx.x * 128;
    const float* xb = x + (size_t)b * CCH * NSP;
    float* xrb = xr + (size_t)b * CCH * NSP;
    const int tid = threadIdx.x, lane = tid & 31, wid = tid >> 5;
    const int wr = wid >> 2, wc = wid & 3;
    const int g = lane >> 2, tk = lane & 3;

    float cf[2][4][4] = {};

    for (int k0 = 0; k0 < CCH; k0 += 16) {
        {
            int r = tid >> 2, kq = (tid & 3) * 4;
            const float* wrow = (r < 32) ? (wk + r * CCH) : (wq + (r - 32) * CCH);
            float4 v = *(const float4*)&wrow[k0 + kq];
            v.x = tf32_rn(v.x); v.y = tf32_rn(v.y);
            v.z = tf32_rn(v.z); v.w = tf32_rn(v.w);
            *(float4*)&sh.ld.sA[r * 20 + kq] = v;
        }
#pragma unroll
        for (int u = 0; u < 2; u++) {
            int idx = tid + u * 256;
            int kr = idx >> 5, nc = (idx & 31) * 4;
            float4 v = *(const float4*)&xb[(size_t)(k0 + kr) * NSP + col0 + nc];
            v.x = tf32_rn(v.x); v.y = tf32_rn(v.y);
            v.z = tf32_rn(v.z); v.w = tf32_rn(v.w);
            // side stream: rounded x for the V branch (each element written once)
            *(float4*)&xrb[(size_t)(k0 + kr) * NSP + col0 + nc] = v;
            sh.ld.sB[(nc + 0) * 20 + kr] = v.x;
            sh.ld.sB[(nc + 1) * 20 + kr] = v.y;
            sh.ld.sB[(nc + 2) * 20 + kr] = v.z;
            sh.ld.sB[(nc + 3) * 20 + kr] = v.w;
        }
        __syncthreads();
#pragma unroll
        for (int ks = 0; ks < 2; ks++) {
            const int ko = ks * 8;
            uint32_t a[2][4], bf[4][2];
#pragma unroll
            for (int i = 0; i < 2; i++) {
                const int ra = (wr * 32 + i * 16 + g) * 20 + ko + tk;
                a[i][0] = __float_as_uint(sh.ld.sA[ra]);
                a[i][1] = __float_as_uint(sh.ld.sA[ra + 8 * 20]);
                a[i][2] = __float_as_uint(sh.ld.sA[ra + 4]);
                a[i][3] = __float_as_uint(sh.ld.sA[ra + 8 * 20 + 4]);
            }
#pragma unroll
            for (int j = 0; j < 4; j++) {
                const int rb = (wc * 32 + j * 8 + g) * 20 + ko + tk;
                bf[j][0] = __float_as_uint(sh.ld.sB[rb]);
                bf[j][1] = __float_as_uint(sh.ld.sB[rb + 4]);
            }
#pragma unroll
            for (int i = 0; i < 2; i++)
#pragma unroll
                for (int j = 0; j < 4; j++) mma_tf32(cf[i][j], a[i], bf[j]);
        }
        __syncthreads();
    }

#pragma unroll
    for (int i = 0; i < 2; i++)
#pragma unroll
        for (int half = 0; half < 2; half++) {
            const int r = wr * 32 + i * 16 + half * 8 + g;
#pragma unroll
            for (int j = 0; j < 4; j++) {
                const int c = wc * 32 + j * 8 + 2 * tk;
                sh.sOut[r * 132 + c]     = cf[i][j][half * 2 + 0];
                sh.sOut[r * 132 + c + 1] = cf[i][j][half * 2 + 1];
            }
        }
    __syncthreads();

    float* kTb = kT + (size_t)b * NSP * CSP;
#pragma unroll
    for (int u = 0; u < 4; u++) {
        int idx = tid + u * 256;
        int nn = idx >> 3, csq = (idx & 7) * 4;
        float4 o;
        o.x = tf32_rn(sh.sOut[(csq + 0) * 132 + nn] + bk[csq + 0]);
        o.y = tf32_rn(sh.sOut[(csq + 1) * 132 + nn] + bk[csq + 1]);
        o.z = tf32_rn(sh.sOut[(csq + 2) * 132 + nn] + bk[csq + 2]);
        o.w = tf32_rn(sh.sOut[(csq + 3) * 132 + nn] + bk[csq + 3]);
        *(float4*)&kTb[(size_t)(col0 + nn) * CSP + csq] = o;
    }

    float* qTb = qT + (size_t)b * NPOOL * CSP;
    const int hp = col0 >> 7;
    {
        int wp = tid >> 3, csq = (tid & 7) * 4;
        float4 o;
        float* oc = &o.x;
#pragma unroll
        for (int t = 0; t < 4; t++) {
            const int cs = csq + t;
            const float* r = &sh.sOut[(32 + cs) * 132];
            float v = fmaxf(fmaxf(r[2 * wp], r[2 * wp + 1]),
                            fmaxf(r[64 + 2 * wp], r[64 + 2 * wp + 1]));
            oc[t] = tf32_rn(v + bq[cs]);
        }
        *(float4*)&qTb[(size_t)(hp * 32 + wp) * CSP + csq] = o;
    }
}

// ============ energy via tf32 mma + exp -> bf16 + partials ====
__global__ __launch_bounds__(256)
void energy_mma(const float* __restrict__ kTg, const float* __restrict__ qTg,
                __nv_bfloat16* __restrict__ attnh, float* __restrict__ part)
{
    __shared__ float sA[128 * 36];
    __shared__ float sB[128 * 36];
    __shared__ float sX[16 * 132];

    const int b  = blockIdx.z;
    const int m0 = blockIdx.y * 128;
    const int n0 = blockIdx.x * 128;
    const float* Ab = kTg + ((size_t)b * NSP + m0) * CSP;
    const float* Bb = qTg + ((size_t)b * NPOOL + n0) * CSP;

    const int tid = threadIdx.x, lane = tid & 31, wid = tid >> 5;
    const int wr = wid >> 2, wc = wid & 3;
    const int g = lane >> 2, tk = lane & 3;

#pragma unroll
    for (int u = 0; u < 4; u++) {
        int idx = tid + u * 256;
        int r = idx >> 3, kq = (idx & 7) * 4;
        *(float4*)&sA[r * 36 + kq] = *(const float4*)&Ab[(size_t)r * CSP + kq];
        *(float4*)&sB[r * 36 + kq] = *(const float4*)&Bb[(size_t)r * CSP + kq];
    }
    __syncthreads();

    float cf[4][4][4] = {};
#pragma unroll
    for (int ks = 0; ks < 4; ks++) {
        const int ko = ks * 8;
        uint32_t a[4][4], bf[4][2];
#pragma unroll
        for (int i = 0; i < 4; i++) {
            const int ra = (wr * 64 + i * 16 + g) * 36 + ko + tk;
            a[i][0] = __float_as_uint(sA[ra]);
            a[i][1] = __float_as_uint(sA[ra + 8 * 36]);
            a[i][2] = __float_as_uint(sA[ra + 4]);
            a[i][3] = __float_as_uint(sA[ra + 8 * 36 + 4]);
        }
#pragma unroll
        for (int j = 0; j < 4; j++) {
            const int rb = (wc * 32 + j * 8 + g) * 36 + ko + tk;
            bf[j][0] = __float_as_uint(sB[rb]);
            bf[j][1] = __float_as_uint(sB[rb + 4]);
        }
#pragma unroll
        for (int i = 0; i < 4; i++)
#pragma unroll
            for (int j = 0; j < 4; j++) mma_tf32(cf[i][j], a[i], bf[j]);
    }

    __nv_bfloat16* Cb = attnh + (size_t)b * NSP * NPOOL;
    float colsum[4][2] = {};
#pragma unroll
    for (int i = 0; i < 4; i++) {
#pragma unroll
        for (int half = 0; half < 2; half++) {
            const int r = m0 + wr * 64 + i * 16 + g + half * 8;
            const size_t ro = (size_t)r * NPOOL;
#pragma unroll
            for (int j = 0; j < 4; j++) {
                const int c = n0 + wc * 32 + j * 8 + 2 * tk;
                float e0 = __expf(cf[i][j][half * 2 + 0]);
                float e1 = __expf(cf[i][j][half * 2 + 1]);
                colsum[j][0] += e0;
                colsum[j][1] += e1;
                *(__nv_bfloat162*)&Cb[ro + c] = __floats2bfloat162_rn(e0, e1);
            }
        }
    }
#pragma unroll
    for (int j = 0; j < 4; j++) {
        const int col = wc * 32 + j * 8 + 2 * tk;
        sX[(wr * 8 + g) * 132 + col]     = colsum[j][0];
        sX[(wr * 8 + g) * 132 + col + 1] = colsum[j][1];
    }
    __syncthreads();
    if (tid < 128) {
        float t = 0.f;
#pragma unroll
        for (int k = 0; k < 16; k++) t += sX[k * 132 + tid];
        part[((size_t)b * 32 + blockIdx.y) * NPOOL + n0 + tid] = t;
    }
}

// ================= V-branch GEMM v2 (inputs pre-rounded tf32-RN) ============
#define GV_SA 2560
#define GV_SB 2176
template<int EPI>
__global__ __launch_bounds__(256)
void gemm_v2(const float* __restrict__ A,
             const float* __restrict__ B,
             const float* __restrict__ bias,
             float* __restrict__ C,
             int M, int N, int K)
{
    __shared__ float sm[2 * GV_SA + 2 * GV_SB];
    float* sX = sm;

    const int b  = blockIdx.z;
    const int r0 = blockIdx.y * 128;
    const int n0 = blockIdx.x * 128;
    const float* Ab = A;
    const float* Bb = B + (size_t)b * K * N;

    const int tid = threadIdx.x, lane = tid & 31, wid = tid >> 5;
    const int wr = wid >> 2, wc = wid & 3;
    const int g = lane >> 2, tk = lane & 3;

    const int a_r = tid >> 1, a_q = (tid & 1) * 2;
    const uint32_t smBase = (uint32_t)__cvta_generic_to_shared(sm);

    auto issue = [&](int k0, int s) {
#pragma unroll
        for (int u = 0; u < 2; u++) {
            int q = a_q + u;
            cpa16(smBase + (s * GV_SA + a_r * 20 + q * 4) * 4,
                  &Ab[(size_t)(r0 + a_r) * K + k0 + q * 4]);
        }
#pragma unroll
        for (int u = 0; u < 2; u++) {
            int idx = tid + u * 256;
            int kr = idx >> 5, nc = (idx & 31) * 4;
            cpa16(smBase + (2 * GV_SA + s * GV_SB + kr * 136 + nc) * 4,
                  &Bb[(size_t)(k0 + kr) * N + n0 + nc]);
        }
        asm volatile("cp.async.commit_group;");
    };

    float cf[4][4][4] = {};
    const int NIT = K / 16;

    issue(0, 0);
    for (int kt = 0; kt < NIT; kt++) {
        const int cur = kt & 1;
        if (kt < NIT - 1) {
            issue((kt + 1) * 16, cur ^ 1);
            asm volatile("cp.async.wait_group 1;");
        } else {
            asm volatile("cp.async.wait_group 0;");
        }
        __syncthreads();

        const float* cA = sm + cur * GV_SA;
        const float* cB = sm + 2 * GV_SA + cur * GV_SB;
#pragma unroll
        for (int ks = 0; ks < 2; ks++) {
            const int ko = ks * 8;
            uint32_t a[4][4], bf[4][2];
#pragma unroll
            for (int i = 0; i < 4; i++) {
                const int ra = (wr * 64 + i * 16 + g) * 20 + ko + tk;
                a[i][0] = __float_as_uint(cA[ra]);
                a[i][1] = __float_as_uint(cA[ra + 8 * 20]);
                a[i][2] = __float_as_uint(cA[ra + 4]);
                a[i][3] = __float_as_uint(cA[ra + 8 * 20 + 4]);
            }
#pragma unroll
            for (int j = 0; j < 4; j++) {
                const int nn = wc * 32 + j * 8 + g;
                bf[j][0] = __float_as_uint(cB[(ko + tk) * 136 + nn]);
                bf[j][1] = __float_as_uint(cB[(ko + tk + 4) * 136 + nn]);
            }
#pragma unroll
            for (int i = 0; i < 4; i++)
#pragma unroll
                for (int j = 0; j < 4; j++) mma_tf32(cf[i][j], a[i], bf[j]);
        }
        __syncthreads();
    }

    if (EPI == 0) {
        float* Cb = C + (size_t)b * M * N;
#pragma unroll
        for (int i = 0; i < 4; i++)
#pragma unroll
            for (int half = 0; half < 2; half++) {
                const int r = r0 + wr * 64 + i * 16 + g + half * 8;
                const float bv = (bias != nullptr) ? bias[r] : 0.f;
                const size_t ro = (size_t)r * N;
#pragma unroll
                for (int j = 0; j < 4; j++) {
                    const int c = n0 + wc * 32 + j * 8 + 2 * tk;
                    float2 o;
                    o.x = cf[i][j][half * 2 + 0] + bv;
                    o.y = cf[i][j][half * 2 + 1] + bv;
                    *(float2*)&Cb[ro + c] = o;
                }
            }
    }

    if (EPI == 1) {
        float* Cp = C + (size_t)b * M * (N / 4);
        const int pcb = n0 >> 2;
#pragma unroll 1
        for (int s = 0; s < 4; s++) {
            if (wr == (s >> 1)) {
#pragma unroll
                for (int ii = 0; ii < 2; ii++) {
                    const int i = (s & 1) * 2 + ii;
#pragma unroll
                    for (int half = 0; half < 2; half++) {
                        const int lr = ii * 16 + half * 8 + g;
#pragma unroll
                        for (int j = 0; j < 4; j++) {
                            const int col = wc * 32 + j * 8 + 2 * tk;
                            sX[lr * 132 + col]     = cf[i][j][half * 2 + 0];
                            sX[lr * 132 + col + 1] = cf[i][j][half * 2 + 1];
                        }
                    }
                }
            }
            __syncthreads();
#pragma unroll
            for (int u = 0; u < 4; u++) {
                int po = tid + u * 256;
                int rr = po >> 5, pc = po & 31;
                float v = fmaxf(fmaxf(sX[rr * 132 + 2 * pc], sX[rr * 132 + 2 * pc + 1]),
                                fmaxf(sX[rr * 132 + 64 + 2 * pc], sX[rr * 132 + 64 + 2 * pc + 1]));
                const int r = r0 + s * 32 + rr;
                Cp[(size_t)r * (N / 4) + pcb + pc] = tf32_rn(v + bias[r]);
            }
            __syncthreads();
        }
    }
}

// ---------------- denominator + v'' ----------------
__global__ void invden_k(const float* __restrict__ part, float* __restrict__ invden)
{
    int idx = blockIdx.x * 256 + threadIdx.x;
    int b  = idx >> 10;
    int np = idx & 1023;
    const float* p = part + (size_t)b * 32 * NPOOL + np;
    float s = 0.f;
#pragma unroll
    for (int i = 0; i < 32; i++) s += p[(size_t)i * NPOOL];
    invden[idx] = 1.f / s;
}

__global__ void scale_v_k(const float* __restrict__ vpr,
                          const float* __restrict__ invden,
                          __nv_bfloat16* __restrict__ vppb)
{
    int idx = blockIdx.x * 256 + threadIdx.x;
    int np = idx & 1023;
    int b  = idx >> 18;
    vppb[idx] = __float2bfloat16_rn(vpr[idx] * invden[b * NPOOL + np]);
}

// ============ final bf16 mma: full-C tile 256x128, cp.async (R7 final2) =====
#define FSTRIDE 12
__global__ __launch_bounds__(256)
void final2_k(const __nv_bfloat16* __restrict__ vpp,
              const __nv_bfloat16* __restrict__ pm,
              const float* __restrict__ bo,
              const float* __restrict__ gamma,
              const float* __restrict__ xres,
              float* __restrict__ out)
{
    __shared__ uint32_t uA[2][256 * FSTRIDE];
    __shared__ uint32_t uB[2][128 * FSTRIDE];

    const int tid = threadIdx.x, lane = tid & 31, wid = tid >> 5;
    const int b  = blockIdx.z;
    const int m0 = blockIdx.x * 128;
    const int wr = wid >> 1;           // 0..3 : c 64-quarter
    const int wc = wid & 1;            // 0..1 : m 64-half
    const int g = lane >> 2, tk = lane & 3;

    const __nv_bfloat16* Ab = vpp + (size_t)b * CCH * NPOOL;
    const __nv_bfloat16* Bb = pm + ((size_t)b * NSP + m0) * NPOOL;

    const int ar = tid >> 1, acq = tid & 1;
    const int br = tid >> 1;
    uint32_t aDst0 = (uint32_t)__cvta_generic_to_shared(&uA[0][ar * FSTRIDE + acq * 4]);
    uint32_t aDst1 = (uint32_t)__cvta_generic_to_shared(&uA[0][(ar + 128) * FSTRIDE + acq * 4]);
    uint32_t bDst  = (uint32_t)__cvta_generic_to_shared(&uB[0][br * FSTRIDE + (tid & 1) * 4]);
    const uint32_t bufStepA = 256 * FSTRIDE * 4;
    const uint32_t bufStepB = 128 * FSTRIDE * 4;

    float cf[4][8][4] = {};

    auto issue = [&](int kt, int s) {
        const int kb = kt * 16;
        cpa16(aDst0 + s * bufStepA, &Ab[(size_t)ar * NPOOL + kb + acq * 8]);
        cpa16(aDst1 + s * bufStepA, &Ab[(size_t)(ar + 128) * NPOOL + kb + acq * 8]);
        cpa16(bDst + s * bufStepB, &Bb[(size_t)br * NPOOL + kb + (tid & 1) * 8]);
        asm volatile("cp.async.commit_group;");
    };

    issue(0, 0);
    for (int kt = 0; kt < NPOOL / 16; kt++) {
        const int cur = kt & 1;
        if (kt < NPOOL / 16 - 1) {
            issue(kt + 1, cur ^ 1);
            asm volatile("cp.async.wait_group 1;");
        } else {
            asm volatile("cp.async.wait_group 0;");
        }
        __syncthreads();

        uint32_t a[4][4], bf[8][2];
#pragma unroll
        for (int i = 0; i < 4; i++) {
            const int ra = (wr * 64 + i * 16 + g) * FSTRIDE + tk;
            a[i][0] = uA[cur][ra];
            a[i][1] = uA[cur][ra + 8 * FSTRIDE];
            a[i][2] = uA[cur][ra + 4];
            a[i][3] = uA[cur][ra + 8 * FSTRIDE + 4];
        }
#pragma unroll
        for (int j = 0; j < 8; j++) {
            const int rb = (wc * 64 + j * 8 + g) * FSTRIDE + tk;
            bf[j][0] = uB[cur][rb];
            bf[j][1] = uB[cur][rb + 4];
        }
#pragma unroll
        for (int i = 0; i < 4; i++)
#pragma unroll
            for (int j = 0; j < 8; j++) mma_bf16(cf[i][j], a[i], bf[j]);
        __syncthreads();
    }

    const float gm = gamma[0];
#pragma unroll
    for (int i = 0; i < 4; i++) {
#pragma unroll
        for (int half = 0; half < 2; half++) {
            const int c = wr * 64 + i * 16 + g + half * 8;
            const float bc = bo[c];
            const size_t ro = ((size_t)b * CCH + c) * NSP;
#pragma unroll
            for (int j = 0; j < 8; j++) {
                const int m = m0 + wc * 64 + j * 8 + 2 * tk;
                float2 xr = *(const float2*)&xres[ro + m];
                float2 o;
                o.x = gm * (cf[i][j][half * 2 + 0] + bc) + xr.x;
                o.y = gm * (cf[i][j][half * 2 + 1] + bc) + xr.y;
                *(float2*)&out[ro + m] = o;
            }
        }
    }
}

// ---------------- launch ----------------
extern "C" void kernel_launch(void* const* d_in, const int* in_sizes, int n_in,
                              void* d_out, int out_size)
{
    const float* x     = (const float*)d_in[0];
    const float* wq    = (const float*)d_in[1];
    const float* bq    = (const float*)d_in[2];
    const float* wk    = (const float*)d_in[3];
    const float* bk    = (const float*)d_in[4];
    const float* wv    = (const float*)d_in[5];
    const float* bv    = (const float*)d_in[6];
    const float* wo    = (const float*)d_in[7];
    const float* bo    = (const float*)d_in[8];
    const float* gamma = (const float*)d_in[9];
    float* out = (float*)d_out;

    float *pkT, *pqT, *pxr, *pwvr, *pwor, *pvp, *pvpr, *ppart, *pinv;
    __nv_bfloat16 *pattnh, *pvppb;
    cudaGetSymbolAddress((void**)&pkT,    g_kT);
    cudaGetSymbolAddress((void**)&pqT,    g_qT);
    cudaGetSymbolAddress((void**)&pxr,    g_xr);
    cudaGetSymbolAddress((void**)&pwvr,   g_wvr);
    cudaGetSymbolAddress((void**)&pwor,   g_wor);
    cudaGetSymbolAddress((void**)&pvp,    g_vpool);
    cudaGetSymbolAddress((void**)&pvpr,   g_vprime);
    cudaGetSymbolAddress((void**)&ppart,  g_part);
    cudaGetSymbolAddress((void**)&pinv,   g_invden);
    cudaGetSymbolAddress((void**)&pattnh, g_attnh);
    cudaGetSymbolAddress((void**)&pvppb,  g_vppb);

    static cudaStream_t s1 = nullptr;
    static cudaEvent_t evFork = nullptr, evQK = nullptr, evJoin = nullptr;
    if (s1 == nullptr) {
        cudaStreamCreateWithFlags(&s1, cudaStreamNonBlocking);
        cudaEventCreateWithFlags(&evFork, cudaEventDisableTiming);
        cudaEventCreateWithFlags(&evQK,   cudaEventDisableTiming);
        cudaEventCreateWithFlags(&evJoin, cudaEventDisableTiming);
    }

    cudaEventRecord(evFork, 0);
    cudaStreamWaitEvent(s1, evFork, 0);

    // s1: tiny weight rounding (independent of x)
    round_w_k<<<(CCH * CCH) / 1024, 256, 0, s1>>>(wv, wo, pwvr, pwor);

    // main: conv_qk (also emits rounded x for the V branch)
    {
        dim3 g(NSP / 128, 1, BATCH);
        conv_qk_mma<<<g, 256>>>(wk, bk, wq, bq, x, pkT, pqT, pxr);
    }
    cudaEventRecord(evQK, 0);
    cudaStreamWaitEvent(s1, evQK, 0);

    // s1: V branch (overlaps energy/invden on main)
    {   // vpool = tf32_rn(maxpool(wvr @ xr) + bv)
        dim3 g(NSP / 128, CCH / 128, BATCH);
        gemm_v2<1><<<g, 256, 0, s1>>>(pwvr, pxr, bv, pvp, CCH, NSP, CCH);
    }
    {   // v' = wor @ vpool
        dim3 g(NPOOL / 128, CCH / 128, BATCH);
        gemm_v2<0><<<g, 256, 0, s1>>>(pwor, pvp, nullptr, pvpr, CCH, NPOOL, CCH);
    }
    cudaEventRecord(evJoin, s1);

    // main: energy -> invden
    {
        dim3 g(NPOOL / 128, NSP / 128, BATCH);
        energy_mma<<<g, 256>>>(pkT, pqT, pattnh, ppart);
    }
    invden_k<<<BATCH * NPOOL / 256, 256>>>(ppart, pinv);

    cudaStreamWaitEvent(0, evJoin, 0);
    scale_v_k<<<BATCH * CCH * NPOOL / 256, 256>>>(pvpr, pinv, pvppb);
    {
        dim3 g(NSP / 128, 1, BATCH);
        final2_k<<<g, 256>>>(pvppb, pattnh, bo, gamma, x, out);
    }
}